// round 9
// baseline (speedup 1.0000x reference)
#include <cuda_runtime.h>
#include <cstdint>

// Problem constants (fixed by setup_inputs)
#define BS 4
#define NN 1024
#define GD 6
#define CC 256
#define HH 8
#define DH 32
#define MC 64
#define HID 16

// ---------------- scratch (device globals; no allocation allowed) ----------
__device__ int   g_nbhd [BS * NN * MC];     // neighbor indices
__device__ float g_q[BS * NN * CC];
__device__ float g_k[BS * NN * CC];
__device__ float g_v[BS * NN * CC];
__device__ float g_ao[BS * NN * CC];        // attention output before W_out
__device__ float g_attn[BS * NN * HH * MC]; // softmaxed attention weights
__device__ unsigned char g_mask[BS * NN];   // normalized mask (0/1)

__device__ __forceinline__ float swishf(float x) {
    return x / (1.0f + __expf(-x));
}

// ---------------- Kernel 0: normalize mask regardless of bool/int32 layout -
__global__ void mask_norm_kernel(const unsigned char* __restrict__ raw) {
    __shared__ int flag;
    if (threadIdx.x == 0) flag = 0;
    __syncthreads();
    int local = 0;
    for (int i = threadIdx.x; i < BS * NN; i += 256)
        if ((i & 3) != 0 && raw[i]) local = 1;
    if (local) atomicOr(&flag, 1);
    __syncthreads();
    bool is_bytes = (flag != 0);
    const int* ri = (const int*)raw;
    for (int i = threadIdx.x; i < BS * NN; i += 256)
        g_mask[i] = is_bytes ? (raw[i] != 0 ? 1 : 0) : (ri[i] != 0 ? 1 : 0);
}

// ---------------- Kernel B: fused distances + top-64 + pass-through copy ---
__global__ void topk_kernel(const float* __restrict__ g, float* __restrict__ out_g) {
    __shared__ unsigned int skey[NN];
    __shared__ unsigned int hist[256];
    __shared__ unsigned int cum[256];
    __shared__ unsigned int warpsum[8];
    __shared__ unsigned int s_prefix, s_total_lt, s_rt;
    __shared__ int s_bin;
    __shared__ unsigned int c_lt, c_eq;

    int row = blockIdx.x;                    // b*N + i
    int b = row >> 10;
    int t = threadIdx.x;                     // 256 threads
    int lane = t & 31, w = t >> 5;

    const float2* base2 = (const float2*)(g + (size_t)row * NN * GD);
    float2* out2 = out_g ? (float2*)(out_g + (size_t)row * NN * GD) : nullptr;
    #pragma unroll
    for (int r = 0; r < 4; r++) {
        int e = t + r * 256;
        float2 p0 = base2[e * 3 + 0];
        float2 p1 = base2[e * 3 + 1];
        float2 p2 = base2[e * 3 + 2];
        float s = p0.x*p0.x + p0.y*p0.y + p1.x*p1.x + p1.y*p1.y + p2.x*p2.x + p2.y*p2.y;
        if (!g_mask[(b << 10) + e]) s = 1e16f;
        skey[e] = __float_as_uint(s);
        if (out2) {
            out2[e * 3 + 0] = p0;
            out2[e * 3 + 1] = p1;
            out2[e * 3 + 2] = p2;
        }
    }
    if (t == 0) { s_prefix = 0u; s_total_lt = 0u; s_rt = MC; }
    __syncthreads();

    #pragma unroll
    for (int pass = 0; pass < 4; pass++) {
        int shift = 24 - pass * 8;
        unsigned int pmask = (pass == 0) ? 0u : (0xFFFFFFFFu << (shift + 8));
        hist[t] = 0u;
        __syncthreads();
        unsigned int prefix = s_prefix;
        #pragma unroll
        for (int r = 0; r < 4; r++) {
            unsigned int key = skey[t + r * 256];
            if ((key & pmask) == prefix)
                atomicAdd(&hist[(key >> shift) & 0xFFu], 1u);
        }
        __syncthreads();
        unsigned int inc = hist[t];
        #pragma unroll
        for (int o = 1; o < 32; o <<= 1) {
            unsigned int u = __shfl_up_sync(0xFFFFFFFFu, inc, o);
            if (lane >= o) inc += u;
        }
        if (lane == 31) warpsum[w] = inc;
        __syncthreads();
        if (w == 0) {
            unsigned int ws = (lane < 8) ? warpsum[lane] : 0u;
            #pragma unroll
            for (int o = 1; o < 8; o <<= 1) {
                unsigned int u = __shfl_up_sync(0xFFFFFFFFu, ws, o);
                if (lane >= o) ws += u;
            }
            if (lane < 8) warpsum[lane] = ws;
        }
        __syncthreads();
        unsigned int incl = inc + (w > 0 ? warpsum[w - 1] : 0u);
        cum[t] = incl;
        __syncthreads();
        unsigned int rt = s_rt;
        unsigned int prev = (t == 0) ? 0u : cum[t - 1];
        if (incl >= rt && prev < rt) s_bin = t;
        __syncthreads();
        if (t == 0) {
            int bin = s_bin;
            unsigned int cb = (bin == 0) ? 0u : cum[bin - 1];
            s_total_lt += cb;
            s_rt = s_rt - cb;
            s_prefix = s_prefix | ((unsigned int)bin << shift);
        }
        __syncthreads();
    }

    unsigned int T = s_prefix;
    unsigned int total_lt = s_total_lt;
    if (t == 0) { c_lt = 0u; c_eq = 0u; }
    __syncthreads();
    int* outp = g_nbhd + row * MC;
    #pragma unroll
    for (int r = 0; r < 4; r++) {
        int e = t + r * 256;
        unsigned int key = skey[e];
        if (key < T) {
            unsigned int pos = atomicAdd(&c_lt, 1u);
            outp[pos] = e;
        } else if (key == T) {
            unsigned int pe = atomicAdd(&c_eq, 1u);
            unsigned int pos = total_lt + pe;
            if (pos < MC) outp[pos] = e;
        }
    }
}

// ---------------- GEMM 128x64 tile, 8x4 microtile, K=256 -------------------
__device__ __forceinline__ void gemm_tile_128x64(
    const float* __restrict__ A, const float* __restrict__ B,
    const float* __restrict__ bias, float* __restrict__ C,
    int mb, int col0)
{
    __shared__ float As[16][132];
    __shared__ float Bsh[16][64];
    float acc[8][4];
    #pragma unroll
    for (int i = 0; i < 8; i++)
        #pragma unroll
        for (int j = 0; j < 4; j++) acc[i][j] = 0.f;

    int t = threadIdx.x;
    int tm = t >> 4, tn = t & 15;

    for (int k0 = 0; k0 < CC; k0 += 16) {
        #pragma unroll
        for (int r = 0; r < 2; r++) {
            int idx = t + r * 256;
            int m = idx >> 2, kq = idx & 3;
            float4 a = *(const float4*)(A + (size_t)(mb + m) * CC + k0 + kq * 4);
            As[kq*4+0][m] = a.x; As[kq*4+1][m] = a.y;
            As[kq*4+2][m] = a.z; As[kq*4+3][m] = a.w;
        }
        {
            int kk = t >> 4, n4 = t & 15;
            float4 b4 = *(const float4*)(B + (size_t)(k0 + kk) * CC + col0 + n4 * 4);
            *(float4*)&Bsh[kk][n4 * 4] = b4;
        }
        __syncthreads();
        #pragma unroll
        for (int kk = 0; kk < 16; kk++) {
            float a[8], b[4];
            #pragma unroll
            for (int i = 0; i < 8; i++) a[i] = As[kk][tm * 8 + i];
            #pragma unroll
            for (int j = 0; j < 4; j++) b[j] = Bsh[kk][tn * 4 + j];
            #pragma unroll
            for (int i = 0; i < 8; i++)
                #pragma unroll
                for (int j = 0; j < 4; j++) acc[i][j] += a[i] * b[j];
        }
        __syncthreads();
    }
    #pragma unroll
    for (int i = 0; i < 8; i++)
        #pragma unroll
        for (int j = 0; j < 4; j++)
            C[(size_t)(mb + tm*8 + i) * CC + col0 + tn*4 + j] = acc[i][j] + bias[col0 + tn*4 + j];
}

__global__ void __launch_bounds__(256) qkv_gemm_kernel(
    const float* __restrict__ A,
    const float* __restrict__ Wq, const float* __restrict__ bq,
    const float* __restrict__ Wk, const float* __restrict__ bk,
    const float* __restrict__ Wv, const float* __restrict__ bv)
{
    int mb = blockIdx.x * 128;
    int yb = blockIdx.y;
    int which = yb >> 2;
    int col0 = (yb & 3) * 64;
    const float* B  = which == 0 ? Wq : (which == 1 ? Wk : Wv);
    const float* bi = which == 0 ? bq : (which == 1 ? bk : bv);
    float* C = which == 0 ? g_q : (which == 1 ? g_k : g_v);
    gemm_tile_128x64(A, B, bi, C, mb, col0);
}

__global__ void __launch_bounds__(256) out_gemm_kernel(
    const float* __restrict__ B, const float* __restrict__ bias,
    float* __restrict__ C)
{
    gemm_tile_128x64(g_ao, B, bias, C, blockIdx.x * 128, blockIdx.y * 64);
}

// ---------------- Kernel D1: loc-MLP + feature scores + softmax ------------
// warp = head h. MLP: lane handles m=lane and m=lane+32 (each weight LDS
// feeds 2 FMAs). Feature dot: lane = d, coalesced K loads, 4 interleaved
// butterfly reductions per group. Warp owns sscore row h throughout.
__global__ void __launch_bounds__(256) score_kernel(
                            const float* __restrict__ g,
                            const float* __restrict__ lW1, const float* __restrict__ lb1,
                            const float* __restrict__ lW2, const float* __restrict__ lb2,
                            const float* __restrict__ lW3, const float* __restrict__ lb3) {
    __shared__ float sW1[HH * GD * HID];
    __shared__ float sB1[HH * HID];
    __shared__ float sW2[HH * HID * HID];
    __shared__ float sB2[HH * HID];
    __shared__ float sW3[HH * HID];
    __shared__ float sB3[HH];
    __shared__ float sng[MC * 7];
    __shared__ float sq[CC];
    __shared__ float sscore[HH * MC];
    __shared__ int   snidx[MC];
    __shared__ int   snm[MC];

    int i = blockIdx.x;
    int b = blockIdx.y;
    int t = threadIdx.x;
    int h = t >> 5;
    int lane = t & 31;
    int row = b * NN + i;

    for (int x = t; x < HH * GD * HID; x += 256) sW1[x] = lW1[x];
    for (int x = t; x < HH * HID;      x += 256) sB1[x] = lb1[x];
    for (int x = t; x < HH * HID * HID;x += 256) sW2[x] = lW2[x];
    for (int x = t; x < HH * HID;      x += 256) sB2[x] = lb2[x];
    for (int x = t; x < HH * HID;      x += 256) sW3[x] = lW3[x];
    if (t < HH) sB3[t] = lb3[t];

    if (t < MC) {
        int id = g_nbhd[row * MC + t];
        snidx[t] = id;
        snm[t] = g_mask[b * NN + id] != 0 ? 1 : 0;
    }
    sq[t] = g_q[(size_t)row * CC + t];
    __syncthreads();

    for (int x = t; x < MC * GD; x += 256) {
        int m = x / GD, gk = x - m * GD;
        sng[m * 7 + gk] = g[(((size_t)row) * NN + snidx[m]) * GD + gk];
    }
    __syncthreads();

    // ---- location MLP (layers 2+3 fused): lane -> m=lane and m=lane+32
    {
        float xa[GD], xb[GD];
        #pragma unroll
        for (int gg = 0; gg < GD; gg++) {
            xa[gg] = sng[lane * 7 + gg];
            xb[gg] = sng[(lane + 32) * 7 + gg];
        }
        float h1a[HID], h1b[HID];
        #pragma unroll
        for (int k2 = 0; k2 < HID; k2++) {
            float aa = sB1[h * HID + k2], ab = aa;
            #pragma unroll
            for (int gg = 0; gg < GD; gg++) {
                float w = sW1[h * (GD * HID) + gg * HID + k2];
                aa += xa[gg] * w; ab += xb[gg] * w;
            }
            h1a[k2] = swishf(aa); h1b[k2] = swishf(ab);
        }
        float oa = sB3[h], ob = oa;
        #pragma unroll
        for (int l = 0; l < HID; l++) {
            float aa = sB2[h * HID + l], ab = aa;
            #pragma unroll
            for (int k2 = 0; k2 < HID; k2++) {
                float w = sW2[h * (HID * HID) + k2 * HID + l];
                aa += h1a[k2] * w; ab += h1b[k2] * w;
            }
            float w3 = sW3[h * HID + l];
            oa += swishf(aa) * w3; ob += swishf(ab) * w3;
        }
        sscore[h * MC + lane]      = swishf(oa);
        sscore[h * MC + lane + 32] = swishf(ob);
    }
    __syncwarp();

    // ---- feature scores: lane = d, coalesced K loads, 4 interleaved
    //      butterfly reductions (independent chains pipeline the shfl latency)
    {
        const float inv = 0.17677669529663687f;  // 1/sqrt(32)
        float qd = sq[h * DH + lane];
        const size_t bN = (size_t)(b * NN);
        #pragma unroll
        for (int mb = 0; mb < MC; mb += 4) {
            float p0 = g_k[(bN + snidx[mb + 0]) * CC + h * DH + lane] * qd;
            float p1 = g_k[(bN + snidx[mb + 1]) * CC + h * DH + lane] * qd;
            float p2 = g_k[(bN + snidx[mb + 2]) * CC + h * DH + lane] * qd;
            float p3 = g_k[(bN + snidx[mb + 3]) * CC + h * DH + lane] * qd;
            #pragma unroll
            for (int o = 16; o > 0; o >>= 1) {
                p0 += __shfl_xor_sync(0xFFFFFFFFu, p0, o);
                p1 += __shfl_xor_sync(0xFFFFFFFFu, p1, o);
                p2 += __shfl_xor_sync(0xFFFFFFFFu, p2, o);
                p3 += __shfl_xor_sync(0xFFFFFFFFu, p3, o);
            }
            if (lane == 0) {
                sscore[h * MC + mb + 0] += p0 * inv;
                sscore[h * MC + mb + 1] += p1 * inv;
                sscore[h * MC + mb + 2] += p2 * inv;
                sscore[h * MC + mb + 3] += p3 * inv;
            }
        }
    }
    __syncwarp();

    // ---- masked softmax over m (warp = head), write to g_attn
    {
        float s0 = snm[lane]      ? sscore[h * MC + lane]      : -1e38f;
        float s1 = snm[lane + 32] ? sscore[h * MC + lane + 32] : -1e38f;
        float mx = fmaxf(s0, s1);
        #pragma unroll
        for (int o = 16; o > 0; o >>= 1)
            mx = fmaxf(mx, __shfl_xor_sync(0xFFFFFFFFu, mx, o));
        float e0 = __expf(s0 - mx), e1 = __expf(s1 - mx);
        float sm = e0 + e1;
        #pragma unroll
        for (int o = 16; o > 0; o >>= 1)
            sm += __shfl_xor_sync(0xFFFFFFFFu, sm, o);
        float invs = 1.0f / sm;
        float* arow = g_attn + (size_t)row * (HH * MC) + h * MC;
        arow[lane]      = e0 * invs;
        arow[lane + 32] = e1 * invs;
    }
}

// ---------------- Kernel D2: AV accumulation (high occupancy) --------------
__global__ void __launch_bounds__(256) av_kernel() {
    __shared__ float sattn[HH * MC];
    __shared__ int   snidx[MC];
    int i = blockIdx.x;
    int b = blockIdx.y;
    int t = threadIdx.x;
    int row = b * NN + i;
    int warp = t >> 5;                        // = head for channel t

    if (t < MC) snidx[t] = g_nbhd[row * MC + t];
    sattn[t]       = g_attn[(size_t)row * (HH * MC) + t];
    sattn[t + 256] = g_attn[(size_t)row * (HH * MC) + t + 256];
    __syncthreads();

    float acc = 0.f;
    #pragma unroll 8
    for (int m = 0; m < MC; m++) {
        int id = snidx[m];
        acc += sattn[warp * MC + m] * g_v[((size_t)(b * NN + id)) * CC + t];
    }
    g_ao[(size_t)row * CC + t] = acc;
}

// ---------------- Kernel F: mask -> float tail -----------------------------
__global__ void mask_out_kernel(float* __restrict__ out_m) {
    int t = blockIdx.x * blockDim.x + threadIdx.x;
    if (t < BS * NN) out_m[t] = g_mask[t] ? 1.0f : 0.0f;
}

// ---------------- launch ---------------------------------------------------
extern "C" void kernel_launch(void* const* d_in, const int* in_sizes, int n_in,
                              void* d_out, int out_size) {
    const float*         pg   = (const float*)d_in[0];
    const float*         cf   = (const float*)d_in[1];
    const unsigned char* mask = (const unsigned char*)d_in[2];
    const float* lW1 = (const float*)d_in[3];
    const float* lb1 = (const float*)d_in[4];
    const float* lW2 = (const float*)d_in[5];
    const float* lb2 = (const float*)d_in[6];
    const float* lW3 = (const float*)d_in[7];
    const float* lb3 = (const float*)d_in[8];
    const float* Wq  = (const float*)d_in[9];
    const float* bq  = (const float*)d_in[10];
    const float* Wk  = (const float*)d_in[11];
    const float* bk  = (const float*)d_in[12];
    const float* Win = (const float*)d_in[13];
    const float* bin = (const float*)d_in[14];
    const float* Wout= (const float*)d_in[15];
    const float* bout= (const float*)d_in[16];

    const size_t GSZ = (size_t)BS * NN * NN * GD;   // 25165824
    const size_t OSZ = (size_t)BS * NN * CC;        // 1048576
    const size_t MSZ = (size_t)BS * NN;             // 4096

    float* out = (float*)d_out;
    float* out_g = nullptr;
    float* out_o = out;
    float* out_m = nullptr;
    size_t osz = (size_t)out_size;
    if (osz == GSZ + OSZ + MSZ)      { out_g = out; out_o = out + GSZ; out_m = out + GSZ + OSZ; }
    else if (osz == GSZ + OSZ)       { out_g = out; out_o = out + GSZ; }
    else if (osz == OSZ + MSZ)       { out_o = out; out_m = out + OSZ; }

    mask_norm_kernel<<<1, 256>>>(mask);
    topk_kernel<<<BS * NN, 256>>>(pg, out_g);
    qkv_gemm_kernel<<<dim3(BS * NN / 128, 12), 256>>>(cf, Wq, bq, Wk, bk, Win, bin);
    score_kernel<<<dim3(NN, BS), 256>>>(pg, lW1, lb1, lW2, lb2, lW3, lb3);
    av_kernel<<<dim3(NN, BS), 256>>>();
    out_gemm_kernel<<<dim3(BS * NN / 128, CC / 64), 256>>>(Wout, bout, out_o);
    if (out_m) mask_out_kernel<<<(BS * NN + 255) / 256, 256>>>(out_m);
}

// round 10
// speedup vs baseline: 1.5215x; 1.5215x over previous
#include <cuda_runtime.h>
#include <cstdint>

// Problem constants (fixed by setup_inputs)
#define BS 4
#define NN 1024
#define GD 6
#define CC 256
#define HH 8
#define DH 32
#define MC 64
#define HID 16

// ---------------- scratch (device globals; no allocation allowed) ----------
__device__ int   g_nbhd [BS * NN * MC];     // neighbor indices
__device__ float g_q[BS * NN * CC];
__device__ float g_k[BS * NN * CC];
__device__ float g_v[BS * NN * CC];
__device__ float g_ao[BS * NN * CC];        // attention output before W_out
__device__ float g_attn[BS * NN * HH * MC]; // softmaxed attention weights
__device__ unsigned char g_mask[BS * NN];   // normalized mask (0/1)

__device__ __forceinline__ float swishf(float x) {
    return x / (1.0f + __expf(-x));
}

// ---------------- Kernel 0: normalize mask regardless of bool/int32 layout -
__global__ void mask_norm_kernel(const unsigned char* __restrict__ raw) {
    __shared__ int flag;
    if (threadIdx.x == 0) flag = 0;
    __syncthreads();
    int local = 0;
    for (int i = threadIdx.x; i < BS * NN; i += 256)
        if ((i & 3) != 0 && raw[i]) local = 1;
    if (local) atomicOr(&flag, 1);
    __syncthreads();
    bool is_bytes = (flag != 0);
    const int* ri = (const int*)raw;
    for (int i = threadIdx.x; i < BS * NN; i += 256)
        g_mask[i] = is_bytes ? (raw[i] != 0 ? 1 : 0) : (ri[i] != 0 ? 1 : 0);
}

// ---------------- Kernel B: fused distances + top-64 + pass-through copy ---
__global__ void topk_kernel(const float* __restrict__ g, float* __restrict__ out_g) {
    __shared__ unsigned int skey[NN];
    __shared__ unsigned int hist[256];
    __shared__ unsigned int cum[256];
    __shared__ unsigned int warpsum[8];
    __shared__ unsigned int s_prefix, s_total_lt, s_rt;
    __shared__ int s_bin;
    __shared__ unsigned int c_lt, c_eq;

    int row = blockIdx.x;                    // b*N + i
    int b = row >> 10;
    int t = threadIdx.x;                     // 256 threads
    int lane = t & 31, w = t >> 5;

    const float2* base2 = (const float2*)(g + (size_t)row * NN * GD);
    float2* out2 = out_g ? (float2*)(out_g + (size_t)row * NN * GD) : nullptr;
    #pragma unroll
    for (int r = 0; r < 4; r++) {
        int e = t + r * 256;
        float2 p0 = base2[e * 3 + 0];
        float2 p1 = base2[e * 3 + 1];
        float2 p2 = base2[e * 3 + 2];
        float s = p0.x*p0.x + p0.y*p0.y + p1.x*p1.x + p1.y*p1.y + p2.x*p2.x + p2.y*p2.y;
        if (!g_mask[(b << 10) + e]) s = 1e16f;
        skey[e] = __float_as_uint(s);
        if (out2) {
            out2[e * 3 + 0] = p0;
            out2[e * 3 + 1] = p1;
            out2[e * 3 + 2] = p2;
        }
    }
    if (t == 0) { s_prefix = 0u; s_total_lt = 0u; s_rt = MC; }
    __syncthreads();

    #pragma unroll
    for (int pass = 0; pass < 4; pass++) {
        int shift = 24 - pass * 8;
        unsigned int pmask = (pass == 0) ? 0u : (0xFFFFFFFFu << (shift + 8));
        hist[t] = 0u;
        __syncthreads();
        unsigned int prefix = s_prefix;
        #pragma unroll
        for (int r = 0; r < 4; r++) {
            unsigned int key = skey[t + r * 256];
            if ((key & pmask) == prefix)
                atomicAdd(&hist[(key >> shift) & 0xFFu], 1u);
        }
        __syncthreads();
        unsigned int inc = hist[t];
        #pragma unroll
        for (int o = 1; o < 32; o <<= 1) {
            unsigned int u = __shfl_up_sync(0xFFFFFFFFu, inc, o);
            if (lane >= o) inc += u;
        }
        if (lane == 31) warpsum[w] = inc;
        __syncthreads();
        if (w == 0) {
            unsigned int ws = (lane < 8) ? warpsum[lane] : 0u;
            #pragma unroll
            for (int o = 1; o < 8; o <<= 1) {
                unsigned int u = __shfl_up_sync(0xFFFFFFFFu, ws, o);
                if (lane >= o) ws += u;
            }
            if (lane < 8) warpsum[lane] = ws;
        }
        __syncthreads();
        unsigned int incl = inc + (w > 0 ? warpsum[w - 1] : 0u);
        cum[t] = incl;
        __syncthreads();
        unsigned int rt = s_rt;
        unsigned int prev = (t == 0) ? 0u : cum[t - 1];
        if (incl >= rt && prev < rt) s_bin = t;
        __syncthreads();
        if (t == 0) {
            int bin = s_bin;
            unsigned int cb = (bin == 0) ? 0u : cum[bin - 1];
            s_total_lt += cb;
            s_rt = s_rt - cb;
            s_prefix = s_prefix | ((unsigned int)bin << shift);
        }
        __syncthreads();
    }

    unsigned int T = s_prefix;
    unsigned int total_lt = s_total_lt;
    if (t == 0) { c_lt = 0u; c_eq = 0u; }
    __syncthreads();
    int* outp = g_nbhd + row * MC;
    #pragma unroll
    for (int r = 0; r < 4; r++) {
        int e = t + r * 256;
        unsigned int key = skey[e];
        if (key < T) {
            unsigned int pos = atomicAdd(&c_lt, 1u);
            outp[pos] = e;
        } else if (key == T) {
            unsigned int pe = atomicAdd(&c_eq, 1u);
            unsigned int pos = total_lt + pe;
            if (pos < MC) outp[pos] = e;
        }
    }
}

// ---------------- GEMM 128x64 tile, 8x4 microtile, K=256 -------------------
__device__ __forceinline__ void gemm_tile_128x64(
    const float* __restrict__ A, const float* __restrict__ B,
    const float* __restrict__ bias, float* __restrict__ C,
    int mb, int col0)
{
    __shared__ float As[16][132];
    __shared__ float Bsh[16][64];
    float acc[8][4];
    #pragma unroll
    for (int i = 0; i < 8; i++)
        #pragma unroll
        for (int j = 0; j < 4; j++) acc[i][j] = 0.f;

    int t = threadIdx.x;
    int tm = t >> 4, tn = t & 15;

    for (int k0 = 0; k0 < CC; k0 += 16) {
        #pragma unroll
        for (int r = 0; r < 2; r++) {
            int idx = t + r * 256;
            int m = idx >> 2, kq = idx & 3;
            float4 a = *(const float4*)(A + (size_t)(mb + m) * CC + k0 + kq * 4);
            As[kq*4+0][m] = a.x; As[kq*4+1][m] = a.y;
            As[kq*4+2][m] = a.z; As[kq*4+3][m] = a.w;
        }
        {
            int kk = t >> 4, n4 = t & 15;
            float4 b4 = *(const float4*)(B + (size_t)(k0 + kk) * CC + col0 + n4 * 4);
            *(float4*)&Bsh[kk][n4 * 4] = b4;
        }
        __syncthreads();
        #pragma unroll
        for (int kk = 0; kk < 16; kk++) {
            float a[8], b[4];
            #pragma unroll
            for (int i = 0; i < 8; i++) a[i] = As[kk][tm * 8 + i];
            #pragma unroll
            for (int j = 0; j < 4; j++) b[j] = Bsh[kk][tn * 4 + j];
            #pragma unroll
            for (int i = 0; i < 8; i++)
                #pragma unroll
                for (int j = 0; j < 4; j++) acc[i][j] += a[i] * b[j];
        }
        __syncthreads();
    }
    #pragma unroll
    for (int i = 0; i < 8; i++)
        #pragma unroll
        for (int j = 0; j < 4; j++)
            C[(size_t)(mb + tm*8 + i) * CC + col0 + tn*4 + j] = acc[i][j] + bias[col0 + tn*4 + j];
}

__global__ void __launch_bounds__(256) qkv_gemm_kernel(
    const float* __restrict__ A,
    const float* __restrict__ Wq, const float* __restrict__ bq,
    const float* __restrict__ Wk, const float* __restrict__ bk,
    const float* __restrict__ Wv, const float* __restrict__ bv)
{
    int mb = blockIdx.x * 128;
    int yb = blockIdx.y;
    int which = yb >> 2;
    int col0 = (yb & 3) * 64;
    const float* B  = which == 0 ? Wq : (which == 1 ? Wk : Wv);
    const float* bi = which == 0 ? bq : (which == 1 ? bk : bv);
    float* C = which == 0 ? g_q : (which == 1 ? g_k : g_v);
    gemm_tile_128x64(A, B, bi, C, mb, col0);
}

__global__ void __launch_bounds__(256) out_gemm_kernel(
    const float* __restrict__ B, const float* __restrict__ bias,
    float* __restrict__ C)
{
    gemm_tile_128x64(g_ao, B, bias, C, blockIdx.x * 128, blockIdx.y * 64);
}

// ---------------- Kernel D1: loc-MLP + feature scores + softmax ------------
// Phase 1 (MLP): warp = head, lane covers m=lane and m=lane+32 — each weight
//   LDS feeds 2 FMAs (halves MLP smem wavefronts).
// Phase 2 (feature): thread = (m = t&63, heads t>>6 and t>>6+4) — 8 float4
//   LDGs per (m,h), no shuffles (the R8 known-good structure).
// Phase 3 (softmax): warp = head.
__global__ void __launch_bounds__(256) score_kernel(
                            const float* __restrict__ g,
                            const float* __restrict__ lW1, const float* __restrict__ lb1,
                            const float* __restrict__ lW2, const float* __restrict__ lb2,
                            const float* __restrict__ lW3, const float* __restrict__ lb3) {
    __shared__ float sW1[HH * GD * HID];
    __shared__ float sB1[HH * HID];
    __shared__ float sW2[HH * HID * HID];
    __shared__ float sB2[HH * HID];
    __shared__ float sW3[HH * HID];
    __shared__ float sB3[HH];
    __shared__ float sng[MC * 7];
    __shared__ float sq[CC];
    __shared__ float sscore[HH * MC];
    __shared__ int   snidx[MC];
    __shared__ int   snm[MC];

    int i = blockIdx.x;
    int b = blockIdx.y;
    int t = threadIdx.x;
    int h = t >> 5;
    int lane = t & 31;
    int row = b * NN + i;

    for (int x = t; x < HH * GD * HID; x += 256) sW1[x] = lW1[x];
    for (int x = t; x < HH * HID;      x += 256) sB1[x] = lb1[x];
    for (int x = t; x < HH * HID * HID;x += 256) sW2[x] = lW2[x];
    for (int x = t; x < HH * HID;      x += 256) sB2[x] = lb2[x];
    for (int x = t; x < HH * HID;      x += 256) sW3[x] = lW3[x];
    if (t < HH) sB3[t] = lb3[t];

    if (t < MC) {
        int id = g_nbhd[row * MC + t];
        snidx[t] = id;
        snm[t] = g_mask[b * NN + id] != 0 ? 1 : 0;
    }
    sq[t] = g_q[(size_t)row * CC + t];
    __syncthreads();

    for (int x = t; x < MC * GD; x += 256) {
        int m = x / GD, gk = x - m * GD;
        sng[m * 7 + gk] = g[(((size_t)row) * NN + snidx[m]) * GD + gk];
    }
    __syncthreads();

    // ---- Phase 1: location MLP (layers 2+3 fused); warp = head
    {
        float xa[GD], xb[GD];
        #pragma unroll
        for (int gg = 0; gg < GD; gg++) {
            xa[gg] = sng[lane * 7 + gg];
            xb[gg] = sng[(lane + 32) * 7 + gg];
        }
        float h1a[HID], h1b[HID];
        #pragma unroll
        for (int k2 = 0; k2 < HID; k2++) {
            float aa = sB1[h * HID + k2], ab = aa;
            #pragma unroll
            for (int gg = 0; gg < GD; gg++) {
                float w = sW1[h * (GD * HID) + gg * HID + k2];
                aa += xa[gg] * w; ab += xb[gg] * w;
            }
            h1a[k2] = swishf(aa); h1b[k2] = swishf(ab);
        }
        float oa = sB3[h], ob = oa;
        #pragma unroll
        for (int l = 0; l < HID; l++) {
            float aa = sB2[h * HID + l], ab = aa;
            #pragma unroll
            for (int k2 = 0; k2 < HID; k2++) {
                float w = sW2[h * (HID * HID) + k2 * HID + l];
                aa += h1a[k2] * w; ab += h1b[k2] * w;
            }
            float w3 = sW3[h * HID + l];
            oa += swishf(aa) * w3; ob += swishf(ab) * w3;
        }
        sscore[h * MC + lane]      = swishf(oa);
        sscore[h * MC + lane + 32] = swishf(ob);
    }
    __syncthreads();

    // ---- Phase 2: feature scores; thread = (m, head pair), no shuffles
    {
        int m = t & 63;
        int hbase = t >> 6;                   // 0..3
        const float* krow = g_k + ((size_t)(b * NN + snidx[m])) * CC;
        const float inv = 0.17677669529663687f;  // 1/sqrt(32)
        #pragma unroll
        for (int p = 0; p < 2; p++) {
            int hh = hbase + p * 4;
            const float4* k4 = (const float4*)(krow + hh * DH);
            const float4* q4 = (const float4*)(sq + hh * DH);
            float f = 0.f;
            #pragma unroll
            for (int j = 0; j < 8; j++) {
                float4 kv = k4[j];
                float4 qv = q4[j];
                f += kv.x*qv.x + kv.y*qv.y + kv.z*qv.z + kv.w*qv.w;
            }
            sscore[hh * MC + m] += f * inv;
        }
    }
    __syncthreads();

    // ---- Phase 3: masked softmax over m (warp = head), write to g_attn
    {
        float s0 = snm[lane]      ? sscore[h * MC + lane]      : -1e38f;
        float s1 = snm[lane + 32] ? sscore[h * MC + lane + 32] : -1e38f;
        float mx = fmaxf(s0, s1);
        #pragma unroll
        for (int o = 16; o > 0; o >>= 1)
            mx = fmaxf(mx, __shfl_xor_sync(0xFFFFFFFFu, mx, o));
        float e0 = __expf(s0 - mx), e1 = __expf(s1 - mx);
        float sm = e0 + e1;
        #pragma unroll
        for (int o = 16; o > 0; o >>= 1)
            sm += __shfl_xor_sync(0xFFFFFFFFu, sm, o);
        float invs = 1.0f / sm;
        float* arow = g_attn + (size_t)row * (HH * MC) + h * MC;
        arow[lane]      = e0 * invs;
        arow[lane + 32] = e1 * invs;
    }
}

// ---------------- Kernel D2: AV accumulation (high occupancy) --------------
__global__ void __launch_bounds__(256) av_kernel() {
    __shared__ float sattn[HH * MC];
    __shared__ int   snidx[MC];
    int i = blockIdx.x;
    int b = blockIdx.y;
    int t = threadIdx.x;
    int row = b * NN + i;
    int warp = t >> 5;                        // = head for channel t

    if (t < MC) snidx[t] = g_nbhd[row * MC + t];
    sattn[t]       = g_attn[(size_t)row * (HH * MC) + t];
    sattn[t + 256] = g_attn[(size_t)row * (HH * MC) + t + 256];
    __syncthreads();

    float acc = 0.f;
    #pragma unroll 8
    for (int m = 0; m < MC; m++) {
        int id = snidx[m];
        acc += sattn[warp * MC + m] * g_v[((size_t)(b * NN + id)) * CC + t];
    }
    g_ao[(size_t)row * CC + t] = acc;
}

// ---------------- Kernel F: mask -> float tail -----------------------------
__global__ void mask_out_kernel(float* __restrict__ out_m) {
    int t = blockIdx.x * blockDim.x + threadIdx.x;
    if (t < BS * NN) out_m[t] = g_mask[t] ? 1.0f : 0.0f;
}

// ---------------- launch ---------------------------------------------------
extern "C" void kernel_launch(void* const* d_in, const int* in_sizes, int n_in,
                              void* d_out, int out_size) {
    const float*         pg   = (const float*)d_in[0];
    const float*         cf   = (const float*)d_in[1];
    const unsigned char* mask = (const unsigned char*)d_in[2];
    const float* lW1 = (const float*)d_in[3];
    const float* lb1 = (const float*)d_in[4];
    const float* lW2 = (const float*)d_in[5];
    const float* lb2 = (const float*)d_in[6];
    const float* lW3 = (const float*)d_in[7];
    const float* lb3 = (const float*)d_in[8];
    const float* Wq  = (const float*)d_in[9];
    const float* bq  = (const float*)d_in[10];
    const float* Wk  = (const float*)d_in[11];
    const float* bk  = (const float*)d_in[12];
    const float* Win = (const float*)d_in[13];
    const float* bin = (const float*)d_in[14];
    const float* Wout= (const float*)d_in[15];
    const float* bout= (const float*)d_in[16];

    const size_t GSZ = (size_t)BS * NN * NN * GD;   // 25165824
    const size_t OSZ = (size_t)BS * NN * CC;        // 1048576
    const size_t MSZ = (size_t)BS * NN;             // 4096

    float* out = (float*)d_out;
    float* out_g = nullptr;
    float* out_o = out;
    float* out_m = nullptr;
    size_t osz = (size_t)out_size;
    if (osz == GSZ + OSZ + MSZ)      { out_g = out; out_o = out + GSZ; out_m = out + GSZ + OSZ; }
    else if (osz == GSZ + OSZ)       { out_g = out; out_o = out + GSZ; }
    else if (osz == OSZ + MSZ)       { out_o = out; out_m = out + OSZ; }

    mask_norm_kernel<<<1, 256>>>(mask);
    topk_kernel<<<BS * NN, 256>>>(pg, out_g);
    qkv_gemm_kernel<<<dim3(BS * NN / 128, 12), 256>>>(cf, Wq, bq, Wk, bk, Win, bin);
    score_kernel<<<dim3(NN, BS), 256>>>(pg, lW1, lb1, lW2, lb2, lW3, lb3);
    av_kernel<<<dim3(NN, BS), 256>>>();
    out_gemm_kernel<<<dim3(BS * NN / 128, CC / 64), 256>>>(Wout, bout, out_o);
    if (out_m) mask_out_kernel<<<(BS * NN + 255) / 256, 256>>>(out_m);
}

// round 11
// speedup vs baseline: 1.7269x; 1.1350x over previous
#include <cuda_runtime.h>
#include <cstdint>

// Problem constants (fixed by setup_inputs)
#define BS 4
#define NN 1024
#define GD 6
#define CC 256
#define HH 8
#define DH 32
#define MC 64
#define HID 16

// ---------------- scratch (device globals; no allocation allowed) ----------
__device__ int   g_nbhd [BS * NN * MC];     // neighbor indices
__device__ float g_q[BS * NN * CC];
__device__ float g_k[BS * NN * CC];
__device__ float g_v[BS * NN * CC];
__device__ float g_ao[BS * NN * CC];        // attention output before W_out
__device__ unsigned char g_mask[BS * NN];   // normalized mask (0/1)

__device__ __forceinline__ float swishf(float x) {
    return x / (1.0f + __expf(-x));
}

// ---------------- Kernel 0: normalize mask regardless of bool/int32 layout -
__global__ void mask_norm_kernel(const unsigned char* __restrict__ raw) {
    __shared__ int flag;
    if (threadIdx.x == 0) flag = 0;
    __syncthreads();
    int local = 0;
    for (int i = threadIdx.x; i < BS * NN; i += 256)
        if ((i & 3) != 0 && raw[i]) local = 1;
    if (local) atomicOr(&flag, 1);
    __syncthreads();
    bool is_bytes = (flag != 0);
    const int* ri = (const int*)raw;
    for (int i = threadIdx.x; i < BS * NN; i += 256)
        g_mask[i] = is_bytes ? (raw[i] != 0 ? 1 : 0) : (ri[i] != 0 ? 1 : 0);
}

// ---------------- Kernel B: fused distances + top-64 + pass-through copy ---
__global__ void topk_kernel(const float* __restrict__ g, float* __restrict__ out_g) {
    __shared__ unsigned int skey[NN];
    __shared__ unsigned int hist[256];
    __shared__ unsigned int cum[256];
    __shared__ unsigned int warpsum[8];
    __shared__ unsigned int s_prefix, s_total_lt, s_rt;
    __shared__ int s_bin;
    __shared__ unsigned int c_lt, c_eq;

    int row = blockIdx.x;                    // b*N + i
    int b = row >> 10;
    int t = threadIdx.x;                     // 256 threads
    int lane = t & 31, w = t >> 5;

    const float2* base2 = (const float2*)(g + (size_t)row * NN * GD);
    float2* out2 = out_g ? (float2*)(out_g + (size_t)row * NN * GD) : nullptr;
    #pragma unroll
    for (int r = 0; r < 4; r++) {
        int e = t + r * 256;
        float2 p0 = base2[e * 3 + 0];
        float2 p1 = base2[e * 3 + 1];
        float2 p2 = base2[e * 3 + 2];
        float s = p0.x*p0.x + p0.y*p0.y + p1.x*p1.x + p1.y*p1.y + p2.x*p2.x + p2.y*p2.y;
        if (!g_mask[(b << 10) + e]) s = 1e16f;
        skey[e] = __float_as_uint(s);
        if (out2) {
            out2[e * 3 + 0] = p0;
            out2[e * 3 + 1] = p1;
            out2[e * 3 + 2] = p2;
        }
    }
    if (t == 0) { s_prefix = 0u; s_total_lt = 0u; s_rt = MC; }
    __syncthreads();

    #pragma unroll
    for (int pass = 0; pass < 4; pass++) {
        int shift = 24 - pass * 8;
        unsigned int pmask = (pass == 0) ? 0u : (0xFFFFFFFFu << (shift + 8));
        hist[t] = 0u;
        __syncthreads();
        unsigned int prefix = s_prefix;
        #pragma unroll
        for (int r = 0; r < 4; r++) {
            unsigned int key = skey[t + r * 256];
            if ((key & pmask) == prefix)
                atomicAdd(&hist[(key >> shift) & 0xFFu], 1u);
        }
        __syncthreads();
        unsigned int inc = hist[t];
        #pragma unroll
        for (int o = 1; o < 32; o <<= 1) {
            unsigned int u = __shfl_up_sync(0xFFFFFFFFu, inc, o);
            if (lane >= o) inc += u;
        }
        if (lane == 31) warpsum[w] = inc;
        __syncthreads();
        if (w == 0) {
            unsigned int ws = (lane < 8) ? warpsum[lane] : 0u;
            #pragma unroll
            for (int o = 1; o < 8; o <<= 1) {
                unsigned int u = __shfl_up_sync(0xFFFFFFFFu, ws, o);
                if (lane >= o) ws += u;
            }
            if (lane < 8) warpsum[lane] = ws;
        }
        __syncthreads();
        unsigned int incl = inc + (w > 0 ? warpsum[w - 1] : 0u);
        cum[t] = incl;
        __syncthreads();
        unsigned int rt = s_rt;
        unsigned int prev = (t == 0) ? 0u : cum[t - 1];
        if (incl >= rt && prev < rt) s_bin = t;
        __syncthreads();
        if (t == 0) {
            int bin = s_bin;
            unsigned int cb = (bin == 0) ? 0u : cum[bin - 1];
            s_total_lt += cb;
            s_rt = s_rt - cb;
            s_prefix = s_prefix | ((unsigned int)bin << shift);
        }
        __syncthreads();
    }

    unsigned int T = s_prefix;
    unsigned int total_lt = s_total_lt;
    if (t == 0) { c_lt = 0u; c_eq = 0u; }
    __syncthreads();
    int* outp = g_nbhd + row * MC;
    #pragma unroll
    for (int r = 0; r < 4; r++) {
        int e = t + r * 256;
        unsigned int key = skey[e];
        if (key < T) {
            unsigned int pos = atomicAdd(&c_lt, 1u);
            outp[pos] = e;
        } else if (key == T) {
            unsigned int pe = atomicAdd(&c_eq, 1u);
            unsigned int pos = total_lt + pe;
            if (pos < MC) outp[pos] = e;
        }
    }
}

// ---------------- GEMM 128x64 tile, 8x4 microtile, K=256 -------------------
__device__ __forceinline__ void gemm_tile_128x64(
    const float* __restrict__ A, const float* __restrict__ B,
    const float* __restrict__ bias, float* __restrict__ C,
    int mb, int col0)
{
    __shared__ float As[16][132];
    __shared__ float Bsh[16][64];
    float acc[8][4];
    #pragma unroll
    for (int i = 0; i < 8; i++)
        #pragma unroll
        for (int j = 0; j < 4; j++) acc[i][j] = 0.f;

    int t = threadIdx.x;
    int tm = t >> 4, tn = t & 15;

    for (int k0 = 0; k0 < CC; k0 += 16) {
        #pragma unroll
        for (int r = 0; r < 2; r++) {
            int idx = t + r * 256;
            int m = idx >> 2, kq = idx & 3;
            float4 a = *(const float4*)(A + (size_t)(mb + m) * CC + k0 + kq * 4);
            As[kq*4+0][m] = a.x; As[kq*4+1][m] = a.y;
            As[kq*4+2][m] = a.z; As[kq*4+3][m] = a.w;
        }
        {
            int kk = t >> 4, n4 = t & 15;
            float4 b4 = *(const float4*)(B + (size_t)(k0 + kk) * CC + col0 + n4 * 4);
            *(float4*)&Bsh[kk][n4 * 4] = b4;
        }
        __syncthreads();
        #pragma unroll
        for (int kk = 0; kk < 16; kk++) {
            float a[8], b[4];
            #pragma unroll
            for (int i = 0; i < 8; i++) a[i] = As[kk][tm * 8 + i];
            #pragma unroll
            for (int j = 0; j < 4; j++) b[j] = Bsh[kk][tn * 4 + j];
            #pragma unroll
            for (int i = 0; i < 8; i++)
                #pragma unroll
                for (int j = 0; j < 4; j++) acc[i][j] += a[i] * b[j];
        }
        __syncthreads();
    }
    #pragma unroll
    for (int i = 0; i < 8; i++)
        #pragma unroll
        for (int j = 0; j < 4; j++)
            C[(size_t)(mb + tm*8 + i) * CC + col0 + tn*4 + j] = acc[i][j] + bias[col0 + tn*4 + j];
}

__global__ void __launch_bounds__(256) qkv_gemm_kernel(
    const float* __restrict__ A,
    const float* __restrict__ Wq, const float* __restrict__ bq,
    const float* __restrict__ Wk, const float* __restrict__ bk,
    const float* __restrict__ Wv, const float* __restrict__ bv)
{
    int mb = blockIdx.x * 128;
    int yb = blockIdx.y;
    int which = yb >> 2;
    int col0 = (yb & 3) * 64;
    const float* B  = which == 0 ? Wq : (which == 1 ? Wk : Wv);
    const float* bi = which == 0 ? bq : (which == 1 ? bk : bv);
    float* C = which == 0 ? g_q : (which == 1 ? g_k : g_v);
    gemm_tile_128x64(A, B, bi, C, mb, col0);
}

__global__ void __launch_bounds__(256) out_gemm_kernel(
    const float* __restrict__ B, const float* __restrict__ bias,
    float* __restrict__ C)
{
    gemm_tile_128x64(g_ao, B, bias, C, blockIdx.x * 128, blockIdx.y * 64);
}

// ---------------- Kernel D: fused loc-MLP + feature + softmax + AV ---------
// Phase 1 (MLP): warp = head, lane covers m=lane and m=lane+32.
// Phase 2 (feature): warp w owns rows m=8w..8w+7; coalesced warp-wide K
//   loads (2x LDG.128/row), 8-lane-group shuffle reduction -> head sums.
// Phase 3 (softmax): warp = head; normalized weights written back to sscore.
// Phase 4 (AV): thread = channel, coalesced V gather (was av_kernel).
__global__ void __launch_bounds__(256) score_kernel(
                            const float* __restrict__ g,
                            const float* __restrict__ lW1, const float* __restrict__ lb1,
                            const float* __restrict__ lW2, const float* __restrict__ lb2,
                            const float* __restrict__ lW3, const float* __restrict__ lb3) {
    __shared__ float sW1[HH * GD * HID];
    __shared__ float sB1[HH * HID];
    __shared__ float sW2[HH * HID * HID];
    __shared__ float sB2[HH * HID];
    __shared__ float sW3[HH * HID];
    __shared__ float sB3[HH];
    __shared__ float sng[MC * 7];
    __shared__ float sq[CC];
    __shared__ float sscore[HH * MC];
    __shared__ int   snidx[MC];
    __shared__ int   snm[MC];

    int i = blockIdx.x;
    int b = blockIdx.y;
    int t = threadIdx.x;
    int h = t >> 5;
    int lane = t & 31;
    int row = b * NN + i;
    const size_t bN = (size_t)(b * NN);

    for (int x = t; x < HH * GD * HID; x += 256) sW1[x] = lW1[x];
    for (int x = t; x < HH * HID;      x += 256) sB1[x] = lb1[x];
    for (int x = t; x < HH * HID * HID;x += 256) sW2[x] = lW2[x];
    for (int x = t; x < HH * HID;      x += 256) sB2[x] = lb2[x];
    for (int x = t; x < HH * HID;      x += 256) sW3[x] = lW3[x];
    if (t < HH) sB3[t] = lb3[t];

    if (t < MC) {
        int id = g_nbhd[row * MC + t];
        snidx[t] = id;
        snm[t] = g_mask[b * NN + id] != 0 ? 1 : 0;
    }
    sq[t] = g_q[(size_t)row * CC + t];
    __syncthreads();

    for (int x = t; x < MC * GD; x += 256) {
        int m = x / GD, gk = x - m * GD;
        sng[m * 7 + gk] = g[(((size_t)row) * NN + snidx[m]) * GD + gk];
    }
    __syncthreads();

    // ---- Phase 1: location MLP (layers 2+3 fused); warp = head
    {
        float xa[GD], xb[GD];
        #pragma unroll
        for (int gg = 0; gg < GD; gg++) {
            xa[gg] = sng[lane * 7 + gg];
            xb[gg] = sng[(lane + 32) * 7 + gg];
        }
        float h1a[HID], h1b[HID];
        #pragma unroll
        for (int k2 = 0; k2 < HID; k2++) {
            float aa = sB1[h * HID + k2], ab = aa;
            #pragma unroll
            for (int gg = 0; gg < GD; gg++) {
                float w = sW1[h * (GD * HID) + gg * HID + k2];
                aa += xa[gg] * w; ab += xb[gg] * w;
            }
            h1a[k2] = swishf(aa); h1b[k2] = swishf(ab);
        }
        float oa = sB3[h], ob = oa;
        #pragma unroll
        for (int l = 0; l < HID; l++) {
            float aa = sB2[h * HID + l], ab = aa;
            #pragma unroll
            for (int k2 = 0; k2 < HID; k2++) {
                float w = sW2[h * (HID * HID) + k2 * HID + l];
                aa += h1a[k2] * w; ab += h1b[k2] * w;
            }
            float w3 = sW3[h * HID + l];
            oa += swishf(aa) * w3; ob += swishf(ab) * w3;
        }
        sscore[h * MC + lane]      = swishf(oa);
        sscore[h * MC + lane + 32] = swishf(ob);
    }
    __syncthreads();

    // ---- Phase 2: feature scores; warp w owns m = 8w..8w+7, coalesced
    {
        const float inv = 0.17677669529663687f;  // 1/sqrt(32)
        const float4* sq4 = (const float4*)sq;
        float4 qa = sq4[lane];        // channels lane*4..lane*4+3   (heads 0-3)
        float4 qb = sq4[lane + 32];   // channels 128+lane*4..+3     (heads 4-7)
        int hg = lane >> 3;           // head group of this lane (0..3)
        #pragma unroll
        for (int r = 0; r < 8; r++) {
            int m = h * 8 + r;        // h doubles as warp id here
            const float4* k4 = (const float4*)(g_k + (bN + snidx[m]) * CC);
            float4 ka = k4[lane];
            float4 kb = k4[lane + 32];
            float fa = ka.x*qa.x + ka.y*qa.y + ka.z*qa.z + ka.w*qa.w;
            float fb = kb.x*qb.x + kb.y*qb.y + kb.z*qb.z + kb.w*qb.w;
            #pragma unroll
            for (int o = 4; o > 0; o >>= 1) {
                fa += __shfl_xor_sync(0xFFFFFFFFu, fa, o);
                fb += __shfl_xor_sync(0xFFFFFFFFu, fb, o);
            }
            if ((lane & 7) == 0) {
                sscore[hg * MC + m]       += fa * inv;
                sscore[(4 + hg) * MC + m] += fb * inv;
            }
        }
    }
    __syncthreads();

    // ---- Phase 3: masked softmax over m (warp = head); weights -> sscore
    {
        float s0 = snm[lane]      ? sscore[h * MC + lane]      : -1e38f;
        float s1 = snm[lane + 32] ? sscore[h * MC + lane + 32] : -1e38f;
        float mx = fmaxf(s0, s1);
        #pragma unroll
        for (int o = 16; o > 0; o >>= 1)
            mx = fmaxf(mx, __shfl_xor_sync(0xFFFFFFFFu, mx, o));
        float e0 = __expf(s0 - mx), e1 = __expf(s1 - mx);
        float sm = e0 + e1;
        #pragma unroll
        for (int o = 16; o > 0; o >>= 1)
            sm += __shfl_xor_sync(0xFFFFFFFFu, sm, o);
        float invs = 1.0f / sm;
        sscore[h * MC + lane]      = e0 * invs;
        sscore[h * MC + lane + 32] = e1 * invs;
    }
    __syncthreads();

    // ---- Phase 4: AV; thread = channel t, head = t/32 = h, coalesced V
    {
        float acc = 0.f;
        #pragma unroll 8
        for (int m = 0; m < MC; m++) {
            acc += sscore[h * MC + m] * g_v[(bN + snidx[m]) * CC + t];
        }
        g_ao[(size_t)row * CC + t] = acc;
    }
}

// ---------------- Kernel F: mask -> float tail -----------------------------
__global__ void mask_out_kernel(float* __restrict__ out_m) {
    int t = blockIdx.x * blockDim.x + threadIdx.x;
    if (t < BS * NN) out_m[t] = g_mask[t] ? 1.0f : 0.0f;
}

// ---------------- launch ---------------------------------------------------
extern "C" void kernel_launch(void* const* d_in, const int* in_sizes, int n_in,
                              void* d_out, int out_size) {
    const float*         pg   = (const float*)d_in[0];
    const float*         cf   = (const float*)d_in[1];
    const unsigned char* mask = (const unsigned char*)d_in[2];
    const float* lW1 = (const float*)d_in[3];
    const float* lb1 = (const float*)d_in[4];
    const float* lW2 = (const float*)d_in[5];
    const float* lb2 = (const float*)d_in[6];
    const float* lW3 = (const float*)d_in[7];
    const float* lb3 = (const float*)d_in[8];
    const float* Wq  = (const float*)d_in[9];
    const float* bq  = (const float*)d_in[10];
    const float* Wk  = (const float*)d_in[11];
    const float* bk  = (const float*)d_in[12];
    const float* Win = (const float*)d_in[13];
    const float* bin = (const float*)d_in[14];
    const float* Wout= (const float*)d_in[15];
    const float* bout= (const float*)d_in[16];

    const size_t GSZ = (size_t)BS * NN * NN * GD;   // 25165824
    const size_t OSZ = (size_t)BS * NN * CC;        // 1048576
    const size_t MSZ = (size_t)BS * NN;             // 4096

    float* out = (float*)d_out;
    float* out_g = nullptr;
    float* out_o = out;
    float* out_m = nullptr;
    size_t osz = (size_t)out_size;
    if (osz == GSZ + OSZ + MSZ)      { out_g = out; out_o = out + GSZ; out_m = out + GSZ + OSZ; }
    else if (osz == GSZ + OSZ)       { out_g = out; out_o = out + GSZ; }
    else if (osz == OSZ + MSZ)       { out_o = out; out_m = out + OSZ; }

    mask_norm_kernel<<<1, 256>>>(mask);
    topk_kernel<<<BS * NN, 256>>>(pg, out_g);
    qkv_gemm_kernel<<<dim3(BS * NN / 128, 12), 256>>>(cf, Wq, bq, Wk, bk, Win, bin);
    score_kernel<<<dim3(NN, BS), 256>>>(pg, lW1, lb1, lW2, lb2, lW3, lb3);
    out_gemm_kernel<<<dim3(BS * NN / 128, CC / 64), 256>>>(Wout, bout, out_o);
    if (out_m) mask_out_kernel<<<(BS * NN + 255) / 256, 256>>>(out_m);
}

// round 12
// speedup vs baseline: 1.7980x; 1.0412x over previous
#include <cuda_runtime.h>
#include <cstdint>

// Problem constants (fixed by setup_inputs)
#define BS 4
#define NN 1024
#define GD 6
#define CC 256
#define HH 8
#define DH 32
#define MC 64
#define HID 16

// ---------------- scratch (device globals; no allocation allowed) ----------
__device__ int   g_nbhd [BS * NN * MC];     // neighbor indices
__device__ float g_q[BS * NN * CC];
__device__ float g_k[BS * NN * CC];
__device__ float g_v[BS * NN * CC];
__device__ float g_ao[BS * NN * CC];        // attention output before W_out
__device__ unsigned char g_mask[BS * NN];   // normalized mask (0/1)

__device__ __forceinline__ float swishf(float x) {
    return x / (1.0f + __expf(-x));
}

// ---------------- Kernel 0: normalize mask regardless of bool/int32 layout -
__global__ void mask_norm_kernel(const unsigned char* __restrict__ raw) {
    __shared__ int flag;
    if (threadIdx.x == 0) flag = 0;
    __syncthreads();
    int local = 0;
    for (int i = threadIdx.x; i < BS * NN; i += 256)
        if ((i & 3) != 0 && raw[i]) local = 1;
    if (local) atomicOr(&flag, 1);
    __syncthreads();
    bool is_bytes = (flag != 0);
    const int* ri = (const int*)raw;
    for (int i = threadIdx.x; i < BS * NN; i += 256)
        g_mask[i] = is_bytes ? (raw[i] != 0 ? 1 : 0) : (ri[i] != 0 ? 1 : 0);
}

// ---------------- Kernel B: fused distances + top-64 + pass-through copy ---
// Thread t owns elements 4t..4t+3 of its row: 6x LDG.128 + 6x STG.128 for the
// pass-through copy (half the transactions of the float2 version).
__global__ void topk_kernel(const float* __restrict__ g, float* __restrict__ out_g) {
    __shared__ unsigned int skey[NN];
    __shared__ unsigned int hist[256];
    __shared__ unsigned int cum[256];
    __shared__ unsigned int warpsum[8];
    __shared__ unsigned int s_prefix, s_total_lt, s_rt;
    __shared__ int s_bin;
    __shared__ unsigned int c_lt, c_eq;

    int row = blockIdx.x;                    // b*N + i
    int b = row >> 10;
    int t = threadIdx.x;                     // 256 threads
    int lane = t & 31, w = t >> 5;

    {
        const float4* gb = (const float4*)(g + (size_t)row * NN * GD);
        float4 v[6];
        #pragma unroll
        for (int j = 0; j < 6; j++) v[j] = gb[t * 6 + j];
        // element e = 4t+j distances
        float d0 = v[0].x*v[0].x + v[0].y*v[0].y + v[0].z*v[0].z + v[0].w*v[0].w
                 + v[1].x*v[1].x + v[1].y*v[1].y;
        float d1 = v[1].z*v[1].z + v[1].w*v[1].w + v[2].x*v[2].x + v[2].y*v[2].y
                 + v[2].z*v[2].z + v[2].w*v[2].w;
        float d2 = v[3].x*v[3].x + v[3].y*v[3].y + v[3].z*v[3].z + v[3].w*v[3].w
                 + v[4].x*v[4].x + v[4].y*v[4].y;
        float d3 = v[4].z*v[4].z + v[4].w*v[4].w + v[5].x*v[5].x + v[5].y*v[5].y
                 + v[5].z*v[5].z + v[5].w*v[5].w;
        uchar4 mk = ((const uchar4*)g_mask)[(b << 8) + t];   // bytes 4t..4t+3 of batch b
        if (!mk.x) d0 = 1e16f;
        if (!mk.y) d1 = 1e16f;
        if (!mk.z) d2 = 1e16f;
        if (!mk.w) d3 = 1e16f;
        skey[4*t + 0] = __float_as_uint(d0);
        skey[4*t + 1] = __float_as_uint(d1);
        skey[4*t + 2] = __float_as_uint(d2);
        skey[4*t + 3] = __float_as_uint(d3);
        if (out_g) {
            float4* ob = (float4*)(out_g + (size_t)row * NN * GD);
            #pragma unroll
            for (int j = 0; j < 6; j++) ob[t * 6 + j] = v[j];
        }
    }
    if (t == 0) { s_prefix = 0u; s_total_lt = 0u; s_rt = MC; }
    __syncthreads();

    #pragma unroll
    for (int pass = 0; pass < 4; pass++) {
        int shift = 24 - pass * 8;
        unsigned int pmask = (pass == 0) ? 0u : (0xFFFFFFFFu << (shift + 8));
        hist[t] = 0u;
        __syncthreads();
        unsigned int prefix = s_prefix;
        #pragma unroll
        for (int r = 0; r < 4; r++) {
            unsigned int key = skey[t + r * 256];
            if ((key & pmask) == prefix)
                atomicAdd(&hist[(key >> shift) & 0xFFu], 1u);
        }
        __syncthreads();
        unsigned int inc = hist[t];
        #pragma unroll
        for (int o = 1; o < 32; o <<= 1) {
            unsigned int u = __shfl_up_sync(0xFFFFFFFFu, inc, o);
            if (lane >= o) inc += u;
        }
        if (lane == 31) warpsum[w] = inc;
        __syncthreads();
        if (w == 0) {
            unsigned int ws = (lane < 8) ? warpsum[lane] : 0u;
            #pragma unroll
            for (int o = 1; o < 8; o <<= 1) {
                unsigned int u = __shfl_up_sync(0xFFFFFFFFu, ws, o);
                if (lane >= o) ws += u;
            }
            if (lane < 8) warpsum[lane] = ws;
        }
        __syncthreads();
        unsigned int incl = inc + (w > 0 ? warpsum[w - 1] : 0u);
        cum[t] = incl;
        __syncthreads();
        unsigned int rt = s_rt;
        unsigned int prev = (t == 0) ? 0u : cum[t - 1];
        if (incl >= rt && prev < rt) s_bin = t;
        __syncthreads();
        if (t == 0) {
            int bin = s_bin;
            unsigned int cb = (bin == 0) ? 0u : cum[bin - 1];
            s_total_lt += cb;
            s_rt = s_rt - cb;
            s_prefix = s_prefix | ((unsigned int)bin << shift);
        }
        __syncthreads();
    }

    unsigned int T = s_prefix;
    unsigned int total_lt = s_total_lt;
    if (t == 0) { c_lt = 0u; c_eq = 0u; }
    __syncthreads();
    int* outp = g_nbhd + row * MC;
    #pragma unroll
    for (int r = 0; r < 4; r++) {
        int e = t + r * 256;
        unsigned int key = skey[e];
        if (key < T) {
            unsigned int pos = atomicAdd(&c_lt, 1u);
            outp[pos] = e;
        } else if (key == T) {
            unsigned int pe = atomicAdd(&c_eq, 1u);
            unsigned int pos = total_lt + pe;
            if (pos < MC) outp[pos] = e;
        }
    }
}

// ---------------- GEMM 128x64 tile, 8x4 microtile, K=256 -------------------
__device__ __forceinline__ void gemm_tile_128x64(
    const float* __restrict__ A, const float* __restrict__ B,
    const float* __restrict__ bias, float* __restrict__ C,
    int mb, int col0)
{
    __shared__ float As[16][132];
    __shared__ float Bsh[16][64];
    float acc[8][4];
    #pragma unroll
    for (int i = 0; i < 8; i++)
        #pragma unroll
        for (int j = 0; j < 4; j++) acc[i][j] = 0.f;

    int t = threadIdx.x;
    int tm = t >> 4, tn = t & 15;

    for (int k0 = 0; k0 < CC; k0 += 16) {
        #pragma unroll
        for (int r = 0; r < 2; r++) {
            int idx = t + r * 256;
            int m = idx >> 2, kq = idx & 3;
            float4 a = *(const float4*)(A + (size_t)(mb + m) * CC + k0 + kq * 4);
            As[kq*4+0][m] = a.x; As[kq*4+1][m] = a.y;
            As[kq*4+2][m] = a.z; As[kq*4+3][m] = a.w;
        }
        {
            int kk = t >> 4, n4 = t & 15;
            float4 b4 = *(const float4*)(B + (size_t)(k0 + kk) * CC + col0 + n4 * 4);
            *(float4*)&Bsh[kk][n4 * 4] = b4;
        }
        __syncthreads();
        #pragma unroll
        for (int kk = 0; kk < 16; kk++) {
            float a[8], b[4];
            #pragma unroll
            for (int i = 0; i < 8; i++) a[i] = As[kk][tm * 8 + i];
            #pragma unroll
            for (int j = 0; j < 4; j++) b[j] = Bsh[kk][tn * 4 + j];
            #pragma unroll
            for (int i = 0; i < 8; i++)
                #pragma unroll
                for (int j = 0; j < 4; j++) acc[i][j] += a[i] * b[j];
        }
        __syncthreads();
    }
    #pragma unroll
    for (int i = 0; i < 8; i++)
        #pragma unroll
        for (int j = 0; j < 4; j++)
            C[(size_t)(mb + tm*8 + i) * CC + col0 + tn*4 + j] = acc[i][j] + bias[col0 + tn*4 + j];
}

__global__ void __launch_bounds__(256) qkv_gemm_kernel(
    const float* __restrict__ A,
    const float* __restrict__ Wq, const float* __restrict__ bq,
    const float* __restrict__ Wk, const float* __restrict__ bk,
    const float* __restrict__ Wv, const float* __restrict__ bv)
{
    int mb = blockIdx.x * 128;
    int yb = blockIdx.y;
    int which = yb >> 2;
    int col0 = (yb & 3) * 64;
    const float* B  = which == 0 ? Wq : (which == 1 ? Wk : Wv);
    const float* bi = which == 0 ? bq : (which == 1 ? bk : bv);
    float* C = which == 0 ? g_q : (which == 1 ? g_k : g_v);
    gemm_tile_128x64(A, B, bi, C, mb, col0);
}

__global__ void __launch_bounds__(256) out_gemm_kernel(
    const float* __restrict__ B, const float* __restrict__ bias,
    float* __restrict__ C)
{
    gemm_tile_128x64(g_ao, B, bias, C, blockIdx.x * 128, blockIdx.y * 64);
}

// ---------------- Kernel D: fused loc-MLP + feature + softmax + AV ---------
__global__ void __launch_bounds__(256) score_kernel(
                            const float* __restrict__ g,
                            const float* __restrict__ lW1, const float* __restrict__ lb1,
                            const float* __restrict__ lW2, const float* __restrict__ lb2,
                            const float* __restrict__ lW3, const float* __restrict__ lb3) {
    __shared__ float sW1[HH * GD * HID];
    __shared__ float sB1[HH * HID];
    __shared__ float sW2[HH * HID * HID];
    __shared__ float sB2[HH * HID];
    __shared__ float sW3[HH * HID];
    __shared__ float sB3[HH];
    __shared__ float sng[MC * 7];
    __shared__ float sq[CC];
    __shared__ float sscore[HH * MC];
    __shared__ int   snidx[MC];
    __shared__ int   snm[MC];

    int i = blockIdx.x;
    int b = blockIdx.y;
    int t = threadIdx.x;
    int h = t >> 5;
    int lane = t & 31;
    int row = b * NN + i;
    const size_t bN = (size_t)(b * NN);

    for (int x = t; x < HH * GD * HID; x += 256) sW1[x] = lW1[x];
    for (int x = t; x < HH * HID;      x += 256) sB1[x] = lb1[x];
    for (int x = t; x < HH * HID * HID;x += 256) sW2[x] = lW2[x];
    for (int x = t; x < HH * HID;      x += 256) sB2[x] = lb2[x];
    for (int x = t; x < HH * HID;      x += 256) sW3[x] = lW3[x];
    if (t < HH) sB3[t] = lb3[t];

    if (t < MC) {
        int id = g_nbhd[row * MC + t];
        snidx[t] = id;
        snm[t] = g_mask[b * NN + id] != 0 ? 1 : 0;
    }
    sq[t] = g_q[(size_t)row * CC + t];
    __syncthreads();

    for (int x = t; x < MC * GD; x += 256) {
        int m = x / GD, gk = x - m * GD;
        sng[m * 7 + gk] = g[(((size_t)row) * NN + snidx[m]) * GD + gk];
    }
    __syncthreads();

    // ---- Phase 1: location MLP (layers 2+3 fused); warp = head
    {
        float xa[GD], xb[GD];
        #pragma unroll
        for (int gg = 0; gg < GD; gg++) {
            xa[gg] = sng[lane * 7 + gg];
            xb[gg] = sng[(lane + 32) * 7 + gg];
        }
        float h1a[HID], h1b[HID];
        #pragma unroll
        for (int k2 = 0; k2 < HID; k2++) {
            float aa = sB1[h * HID + k2], ab = aa;
            #pragma unroll
            for (int gg = 0; gg < GD; gg++) {
                float w = sW1[h * (GD * HID) + gg * HID + k2];
                aa += xa[gg] * w; ab += xb[gg] * w;
            }
            h1a[k2] = swishf(aa); h1b[k2] = swishf(ab);
        }
        float oa = sB3[h], ob = oa;
        #pragma unroll
        for (int l = 0; l < HID; l++) {
            float aa = sB2[h * HID + l], ab = aa;
            #pragma unroll
            for (int k2 = 0; k2 < HID; k2++) {
                float w = sW2[h * (HID * HID) + k2 * HID + l];
                aa += h1a[k2] * w; ab += h1b[k2] * w;
            }
            float w3 = sW3[h * HID + l];
            oa += swishf(aa) * w3; ob += swishf(ab) * w3;
        }
        sscore[h * MC + lane]      = swishf(oa);
        sscore[h * MC + lane + 32] = swishf(ob);
    }
    __syncthreads();

    // ---- Phase 2: feature scores; warp w owns m = 8w..8w+7, coalesced
    {
        const float inv = 0.17677669529663687f;  // 1/sqrt(32)
        const float4* sq4 = (const float4*)sq;
        float4 qa = sq4[lane];
        float4 qb = sq4[lane + 32];
        int hg = lane >> 3;
        #pragma unroll
        for (int r = 0; r < 8; r++) {
            int m = h * 8 + r;
            const float4* k4 = (const float4*)(g_k + (bN + snidx[m]) * CC);
            float4 ka = k4[lane];
            float4 kb = k4[lane + 32];
            float fa = ka.x*qa.x + ka.y*qa.y + ka.z*qa.z + ka.w*qa.w;
            float fb = kb.x*qb.x + kb.y*qb.y + kb.z*qb.z + kb.w*qb.w;
            #pragma unroll
            for (int o = 4; o > 0; o >>= 1) {
                fa += __shfl_xor_sync(0xFFFFFFFFu, fa, o);
                fb += __shfl_xor_sync(0xFFFFFFFFu, fb, o);
            }
            if ((lane & 7) == 0) {
                sscore[hg * MC + m]       += fa * inv;
                sscore[(4 + hg) * MC + m] += fb * inv;
            }
        }
    }
    __syncthreads();

    // ---- Phase 3: masked softmax over m (warp = head); weights -> sscore
    {
        float s0 = snm[lane]      ? sscore[h * MC + lane]      : -1e38f;
        float s1 = snm[lane + 32] ? sscore[h * MC + lane + 32] : -1e38f;
        float mx = fmaxf(s0, s1);
        #pragma unroll
        for (int o = 16; o > 0; o >>= 1)
            mx = fmaxf(mx, __shfl_xor_sync(0xFFFFFFFFu, mx, o));
        float e0 = __expf(s0 - mx), e1 = __expf(s1 - mx);
        float sm = e0 + e1;
        #pragma unroll
        for (int o = 16; o > 0; o >>= 1)
            sm += __shfl_xor_sync(0xFFFFFFFFu, sm, o);
        float invs = 1.0f / sm;
        sscore[h * MC + lane]      = e0 * invs;
        sscore[h * MC + lane + 32] = e1 * invs;
    }
    __syncthreads();

    // ---- Phase 4: AV; thread = channel t, head = t/32 = h, coalesced V
    {
        float acc = 0.f;
        #pragma unroll 8
        for (int m = 0; m < MC; m++) {
            acc += sscore[h * MC + m] * g_v[(bN + snidx[m]) * CC + t];
        }
        g_ao[(size_t)row * CC + t] = acc;
    }
}

// ---------------- Kernel F: mask -> float tail -----------------------------
__global__ void mask_out_kernel(float* __restrict__ out_m) {
    int t = blockIdx.x * blockDim.x + threadIdx.x;
    if (t < BS * NN) out_m[t] = g_mask[t] ? 1.0f : 0.0f;
}

// ---------------- launch ---------------------------------------------------
extern "C" void kernel_launch(void* const* d_in, const int* in_sizes, int n_in,
                              void* d_out, int out_size) {
    const float*         pg   = (const float*)d_in[0];
    const float*         cf   = (const float*)d_in[1];
    const unsigned char* mask = (const unsigned char*)d_in[2];
    const float* lW1 = (const float*)d_in[3];
    const float* lb1 = (const float*)d_in[4];
    const float* lW2 = (const float*)d_in[5];
    const float* lb2 = (const float*)d_in[6];
    const float* lW3 = (const float*)d_in[7];
    const float* lb3 = (const float*)d_in[8];
    const float* Wq  = (const float*)d_in[9];
    const float* bq  = (const float*)d_in[10];
    const float* Wk  = (const float*)d_in[11];
    const float* bk  = (const float*)d_in[12];
    const float* Win = (const float*)d_in[13];
    const float* bin = (const float*)d_in[14];
    const float* Wout= (const float*)d_in[15];
    const float* bout= (const float*)d_in[16];

    const size_t GSZ = (size_t)BS * NN * NN * GD;   // 25165824
    const size_t OSZ = (size_t)BS * NN * CC;        // 1048576
    const size_t MSZ = (size_t)BS * NN;             // 4096

    float* out = (float*)d_out;
    float* out_g = nullptr;
    float* out_o = out;
    float* out_m = nullptr;
    size_t osz = (size_t)out_size;
    if (osz == GSZ + OSZ + MSZ)      { out_g = out; out_o = out + GSZ; out_m = out + GSZ + OSZ; }
    else if (osz == GSZ + OSZ)       { out_g = out; out_o = out + GSZ; }
    else if (osz == OSZ + MSZ)       { out_o = out; out_m = out + OSZ; }

    // Side stream + events for fork/join graph (created once on the first,
    // non-captured correctness call; reused identically thereafter).
    static cudaStream_t s1 = nullptr;
    static cudaEvent_t evA = nullptr, evB = nullptr;
    if (s1 == nullptr) {
        cudaStreamCreateWithFlags(&s1, cudaStreamNonBlocking);
        cudaEventCreateWithFlags(&evA, cudaEventDisableTiming);
        cudaEventCreateWithFlags(&evB, cudaEventDisableTiming);
    }

    mask_norm_kernel<<<1, 256>>>(mask);
    cudaEventRecord(evA, 0);
    cudaStreamWaitEvent(s1, evA, 0);

    // Side stream: QKV GEMM (independent of topk) + mask tail
    qkv_gemm_kernel<<<dim3(BS * NN / 128, 12), 256, 0, s1>>>(cf, Wq, bq, Wk, bk, Win, bin);
    if (out_m) mask_out_kernel<<<(BS * NN + 255) / 256, 256, 0, s1>>>(out_m);
    cudaEventRecord(evB, s1);

    // Main stream: topk overlaps with qkv
    topk_kernel<<<BS * NN, 256>>>(pg, out_g);
    cudaStreamWaitEvent(0, evB, 0);
    score_kernel<<<dim3(NN, BS), 256>>>(pg, lW1, lb1, lW2, lb2, lW3, lb3);
    out_gemm_kernel<<<dim3(BS * NN / 128, CC / 64), 256>>>(Wout, bout, out_o);
}